// round 10
// baseline (speedup 1.0000x reference)
#include <cuda_runtime.h>
#include <math.h>

__device__ float g_Q[512 * 192];
__device__ float g_K[512 * 192];
__device__ float g_V[512 * 192];
__device__ float g_QP[512 * 144];
__device__ float g_KP[512 * 144];
__device__ float g_VP[512 * 288];
__device__ float g_QG[512 * 144];
__device__ float g_KG[512 * 144];
__device__ float g_VG[512 * 288];
__device__ float g_L[(size_t)512 * 512 * 12];   // logits [n][m][h]
__device__ float g_F[512 * 2112];               // feats  [n][h*176 + f]
__device__ float g_EP[4 * 512 * 384];           // split-K partials

// ---------------- kProj: fused projection GEMM, 512 x 1152, K=384 (validated) ----------------
__device__ __forceinline__ void segSelW(int c,
    const float* Wq, const float* Wk, const float* Wv,
    const float* Wqp, const float* Wkp, const float* Wvp,
    const float*& W, int& lc, int& sn)
{
    if (c < 192)      { W = Wq;  lc = c;       sn = 192; }
    else if (c < 384) { W = Wk;  lc = c - 192; sn = 192; }
    else if (c < 576) { W = Wv;  lc = c - 384; sn = 192; }
    else if (c < 720) { W = Wqp; lc = c - 576; sn = 144; }
    else if (c < 864) { W = Wkp; lc = c - 720; sn = 144; }
    else              { W = Wvp; lc = c - 864; sn = 288; }
}

__device__ __forceinline__ void segSelO(int c,
    const float* bq, const float* bk, const float* bv,
    const float* bqp, const float* bkp, const float* bvp,
    float*& out, const float*& bia, int& lc, int& sn)
{
    if (c < 192)      { out = g_Q;  bia = bq;  lc = c;       sn = 192; }
    else if (c < 384) { out = g_K;  bia = bk;  lc = c - 192; sn = 192; }
    else if (c < 576) { out = g_V;  bia = bv;  lc = c - 384; sn = 192; }
    else if (c < 720) { out = g_QP; bia = bqp; lc = c - 576; sn = 144; }
    else if (c < 864) { out = g_KP; bia = bkp; lc = c - 720; sn = 144; }
    else              { out = g_VP; bia = bvp; lc = c - 864; sn = 288; }
}

__global__ void __launch_bounds__(256) kProj(
    const float* __restrict__ s,
    const float* __restrict__ Wq,  const float* __restrict__ bq,
    const float* __restrict__ Wk,  const float* __restrict__ bk,
    const float* __restrict__ Wv,  const float* __restrict__ bv,
    const float* __restrict__ Wqp, const float* __restrict__ bqp,
    const float* __restrict__ Wkp, const float* __restrict__ bkp,
    const float* __restrict__ Wvp, const float* __restrict__ bvp)
{
    __shared__ float As[32 * 68];
    __shared__ float Bs[32 * 68];
    const int t  = threadIdx.x;
    const int c0 = blockIdx.x * 64;
    const int r0 = blockIdx.y * 64;
    const int tx = t % 16, ty = t / 16;

    float acc[4][4];
    #pragma unroll
    for (int i = 0; i < 4; i++)
        #pragma unroll
        for (int j = 0; j < 4; j++) acc[i][j] = 0.f;

    for (int kt = 0; kt < 384; kt += 32) {
        __syncthreads();
        #pragma unroll
        for (int ii = 0; ii < 2; ii++) {
            int i4 = t + 256 * ii;
            int row = i4 >> 3, kq = i4 & 7;
            float4 a = *(const float4*)(s + (size_t)(r0 + row) * 384 + kt + kq * 4);
            As[(kq * 4 + 0) * 68 + row] = a.x;
            As[(kq * 4 + 1) * 68 + row] = a.y;
            As[(kq * 4 + 2) * 68 + row] = a.z;
            As[(kq * 4 + 3) * 68 + row] = a.w;
        }
        #pragma unroll
        for (int ii = 0; ii < 8; ii++) {
            int i = t + 256 * ii;
            int k = i >> 6, c = i & 63;
            const float* W; int lc, sn;
            segSelW(c0 + c, Wq, Wk, Wv, Wqp, Wkp, Wvp, W, lc, sn);
            Bs[k * 68 + c] = W[(size_t)(kt + k) * sn + lc];
        }
        __syncthreads();
        #pragma unroll
        for (int k = 0; k < 32; k++) {
            float4 a = *(const float4*)&As[k * 68 + ty * 4];
            float4 b = *(const float4*)&Bs[k * 68 + tx * 4];
            float av[4] = {a.x, a.y, a.z, a.w};
            float bw[4] = {b.x, b.y, b.z, b.w};
            #pragma unroll
            for (int i = 0; i < 4; i++)
                #pragma unroll
                for (int j = 0; j < 4; j++) acc[i][j] += av[i] * bw[j];
        }
    }
    float* out; const float* bia; int lc, sn;
    segSelO(c0 + tx * 4, bq, bk, bv, bqp, bkp, bvp, out, bia, lc, sn);
    float b0 = bia[lc], b1 = bia[lc + 1], b2 = bia[lc + 2], b3 = bia[lc + 3];
    #pragma unroll
    for (int i = 0; i < 4; i++) {
        int row = r0 + ty * 4 + i;
        float4 v = {acc[i][0] + b0, acc[i][1] + b1, acc[i][2] + b2, acc[i][3] + b3};
        *(float4*)(out + (size_t)row * sn + lc) = v;
    }
}

// ---------------- pTrans (validated) ----------------
__global__ void pTrans(const float* __restrict__ trans, const float* __restrict__ rot)
{
    const int n = blockIdx.x, t = threadIdx.x;   // 192 threads
    const float* R = rot + n * 9;
    const float T0 = trans[n * 3], T1 = trans[n * 3 + 1], T2 = trans[n * 3 + 2];
    const float* src; float* dst; int li;
    if (t < 48)      { src = g_QP + n * 144; dst = g_QG + n * 144; li = t; }
    else if (t < 96) { src = g_KP + n * 144; dst = g_KG + n * 144; li = t - 48; }
    else             { src = g_VP + n * 288; dst = g_VG + n * 288; li = t - 96; }
    float p0 = src[li * 3], p1 = src[li * 3 + 1], p2 = src[li * 3 + 2];
    dst[li * 3 + 0] = R[0] * p0 + R[1] * p1 + R[2] * p2 + T0;
    dst[li * 3 + 1] = R[3] * p0 + R[4] * p1 + R[5] * p2 + T1;
    dst[li * 3 + 2] = R[6] * p0 + R[7] * p1 + R[8] * p2 + T2;
}

// ---------------- pLogits3: 2 query rows per CTA (validated) ----------------
__global__ void __launch_bounds__(512) pLogits3(
    const float* __restrict__ z, const float* __restrict__ trans,
    const float* __restrict__ Wb, const float* __restrict__ bb,
    const float* __restrict__ de, const float* __restrict__ sl,
    const float* __restrict__ hw)
{
    __shared__ float q2[384], qg2[288], sWb[1536], ph[36], shw[12], sbb[12];
    const int n0 = blockIdx.x * 2;
    const int m = threadIdx.x;   // 512 threads, one m each
    for (int i = m; i < 384; i += 512) q2[i]  = g_Q[(size_t)(n0 + i / 192) * 192 + i % 192];
    for (int i = m; i < 288; i += 512) qg2[i] = g_QG[(size_t)(n0 + i / 144) * 144 + i % 144];
    for (int i = m; i < 1536; i += 512) sWb[i] = Wb[i];
    if (m < 12) {
        shw[m] = hw[m];
        sbb[m] = bb[m];
        float a = sl[m], b2 = sl[12 + m], c = sl[24 + m];
        float mx = fmaxf(a, fmaxf(b2, c));
        float ea = expf(a - mx), eb = expf(b2 - mx), ec = expf(c - mx);
        float inv = 1.f / (ea + eb + ec);
        ph[m] = ea * inv; ph[12 + m] = eb * inv; ph[24 + m] = ec * inv;
    }
    __syncthreads();

    float pb0[12], pb1[12];
    #pragma unroll
    for (int h = 0; h < 12; h++) { pb0[h] = sbb[h]; pb1[h] = sbb[h]; }
    const float4* zp0 = (const float4*)(z + ((size_t)n0 * 512 + m) * 128);
    const float4* zp1 = (const float4*)(z + ((size_t)(n0 + 1) * 512 + m) * 128);
    #pragma unroll 2
    for (int c4 = 0; c4 < 32; c4++) {
        float4 a = zp0[c4];
        float4 b = zp1[c4];
        const float* w = &sWb[c4 * 48];
        #pragma unroll
        for (int h = 0; h < 12; h++) {
            float w0 = w[h], w1 = w[12 + h], w2 = w[24 + h], w3 = w[36 + h];
            pb0[h] += a.x * w0 + a.y * w1 + a.z * w2 + a.w * w3;
            pb1[h] += b.x * w0 + b.y * w1 + b.z * w2 + b.w * w3;
        }
    }

    const float tmx = trans[m * 3], tmy = trans[m * 3 + 1], tmz = trans[m * 3 + 2];
    float d0, d1;
    {
        float dx = trans[n0 * 3]     - tmx;
        float dy = trans[n0 * 3 + 1] - tmy;
        float dz = trans[n0 * 3 + 2] - tmz;
        d0 = sqrtf(dx * dx + dy * dy + dz * dz);
        dx = trans[(n0 + 1) * 3]     - tmx;
        dy = trans[(n0 + 1) * 3 + 1] - tmy;
        dz = trans[(n0 + 1) * 3 + 2] - tmz;
        d1 = sqrtf(dx * dx + dy * dy + dz * dz);
    }
    int bin0 = min(max((int)ceilf(d0 * 2.0f) - 1, 0), 63);
    int bin1 = min(max((int)ceilf(d1 * 2.0f) - 1, 0), 63);
    float lo0 = (d0 <= 5.0f) ? 1.f : 0.f;
    float me0 = (d0 > 5.0f && d0 <= 15.0f) ? 1.f : 0.f;
    float lo1 = (d1 <= 5.0f) ? 1.f : 0.f;
    float me1 = (d1 > 5.0f && d1 <= 15.0f) ? 1.f : 0.f;

    const float* kr = g_K  + (size_t)m * 192;
    const float* kg = g_KG + (size_t)m * 144;
    float* Lp0 = g_L + ((size_t)n0 * 512 + m) * 12;
    float* Lp1 = g_L + ((size_t)(n0 + 1) * 512 + m) * 12;
    #pragma unroll
    for (int h = 0; h < 12; h++) {
        float sc0 = 0.f, sc1 = 0.f;
        #pragma unroll
        for (int c = 0; c < 16; c++) {
            float kv = kr[h * 16 + c];
            sc0 += q2[h * 16 + c] * kv;
            sc1 += q2[192 + h * 16 + c] * kv;
        }
        float pd0 = 0.f, pd1 = 0.f;
        #pragma unroll
        for (int i = 0; i < 12; i++) {
            float kv = kg[h * 12 + i];
            float f0 = qg2[h * 12 + i] - kv;
            float f1 = qg2[144 + h * 12 + i] - kv;
            pd0 += f0 * f0;
            pd1 += f1 * f1;
        }
        Lp0[h] = 0.25f * sc0 - 0.5f * pd0 * shw[h] + pb0[h]
               + de[bin0 * 12 + h] + lo0 * ph[h] + me0 * ph[12 + h] + ph[24 + h];
        Lp1[h] = 0.25f * sc1 - 0.5f * pd1 * shw[h] + pb1[h]
               + de[bin1 * 12 + h] + lo1 * ph[h] + me1 * ph[12 + h] + ph[24 + h];
    }
}

// ---------------- kApply4: fused softmax + apply, all operands smem-staged ----------------
// 672 threads: [0,384) pair (warp=head, lane=4 cols), [384,576) scalar, [576,672) pts.
// dynamic smem layout (floats): at[6144] | zt[32*128] | vt[32*192] | vgt[32*288]
#define AT_OFF  0
#define ZT_OFF  6144
#define VT_OFF  10240
#define VGT_OFF 16384
#define APPLY_SMEM_FLOATS 25600

__global__ void __launch_bounds__(672) kApply4(
    const float* __restrict__ z, const float* __restrict__ trans,
    const float* __restrict__ rot)
{
    extern __shared__ float sm[];
    float* at  = sm + AT_OFF;
    float* zt  = sm + ZT_OFF;
    float* vt  = sm + VT_OFF;
    float* vgt = sm + VGT_OFF;
    const int n = blockIdx.x, t = threadIdx.x;
    for (int i = t; i < 6144; i += 672) at[i] = g_L[(size_t)n * 6144 + i];
    __syncthreads();

    // in-place softmax, warp per head (validated)
    const int wid = t >> 5, lane = t & 31;
    if (wid < 12) {
        const int h = wid;
        float mx = -1e30f;
        #pragma unroll
        for (int r = 0; r < 16; r++) mx = fmaxf(mx, at[(lane + 32 * r) * 12 + h]);
        #pragma unroll
        for (int o = 16; o; o >>= 1) mx = fmaxf(mx, __shfl_xor_sync(0xffffffffu, mx, o));
        float ssum = 0.f;
        #pragma unroll
        for (int r = 0; r < 16; r++) ssum += expf(at[(lane + 32 * r) * 12 + h] - mx);
        #pragma unroll
        for (int o = 16; o; o >>= 1) ssum += __shfl_xor_sync(0xffffffffu, ssum, o);
        const float inv = 1.0f / ssum;
        #pragma unroll
        for (int r = 0; r < 16; r++) {
            int mm = lane + 32 * r;
            at[mm * 12 + h] = expf(at[mm * 12 + h] - mx) * inv;
        }
    }

    // role setup
    const int hq = wid;                 // pair head (t<384)
    const int cq = lane * 4;            // pair cols
    float pacc[4] = {0.f, 0.f, 0.f, 0.f};
    const int js = t - 384;             // scalar: 0..191 -> h=js/16
    const int hs = (js >= 0) ? js / 16 : 0;
    float sacc = 0.f;
    const int jp = t - 576;             // pts: 0..95 -> hp=jp/8
    const int hp = (jp >= 0) ? jp / 8 : 0;
    float a0 = 0.f, a1 = 0.f, a2 = 0.f;

    for (int mt = 0; mt < 16; mt++) {
        const int m0 = mt * 32;
        __syncthreads();
        // stage z (1024 f4), V (1536 f4), VG (2304 f4) tiles — coalesced
        for (int i4 = t; i4 < 1024; i4 += 672) {
            int mm = i4 >> 5, c4 = i4 & 31;
            *(float4*)&zt[mm * 128 + c4 * 4] =
                *(const float4*)(z + ((size_t)n * 512 + m0 + mm) * 128 + c4 * 4);
        }
        for (int i4 = t; i4 < 1536; i4 += 672) {
            int mm = i4 / 48, c4 = i4 % 48;
            *(float4*)&vt[mm * 192 + c4 * 4] =
                *(const float4*)(g_V + (size_t)(m0 + mm) * 192 + c4 * 4);
        }
        for (int i4 = t; i4 < 2304; i4 += 672) {
            int mm = i4 / 72, c4 = i4 % 72;
            *(float4*)&vgt[mm * 288 + c4 * 4] =
                *(const float4*)(g_VG + (size_t)(m0 + mm) * 288 + c4 * 4);
        }
        __syncthreads();
        if (t < 384) {
            #pragma unroll 8
            for (int mm = 0; mm < 32; mm++) {
                float p = at[(m0 + mm) * 12 + hq];
                float4 zz = *(const float4*)&zt[mm * 128 + cq];
                pacc[0] += p * zz.x; pacc[1] += p * zz.y;
                pacc[2] += p * zz.z; pacc[3] += p * zz.w;
            }
        } else if (t < 576) {
            #pragma unroll 8
            for (int mm = 0; mm < 32; mm++)
                sacc += at[(m0 + mm) * 12 + hs] * vt[mm * 192 + js];
        } else {
            #pragma unroll 8
            for (int mm = 0; mm < 32; mm++) {
                float pm = at[(m0 + mm) * 12 + hp];
                const float* vg = &vgt[mm * 288 + jp * 3];
                a0 += pm * vg[0]; a1 += pm * vg[1]; a2 += pm * vg[2];
            }
        }
    }

    if (t < 384) {
        float4 v = {pacc[0], pacc[1], pacc[2], pacc[3]};
        *(float4*)(g_F + (size_t)n * 2112 + hq * 176 + 48 + cq) = v;
    } else if (t < 576) {
        g_F[(size_t)n * 2112 + hs * 176 + (js % 16)] = sacc;
    } else {
        const int pp = jp % 8;
        a0 -= trans[n * 3]; a1 -= trans[n * 3 + 1]; a2 -= trans[n * 3 + 2];
        const float* R = rot + n * 9;
        float lx = R[0] * a0 + R[3] * a1 + R[6] * a2;   // R^T
        float ly = R[1] * a0 + R[4] * a1 + R[7] * a2;
        float lz = R[2] * a0 + R[5] * a1 + R[8] * a2;
        float* Fh = g_F + (size_t)n * 2112 + hp * 176;
        Fh[16 + pp * 3]     = lx;
        Fh[16 + pp * 3 + 1] = ly;
        Fh[16 + pp * 3 + 2] = lz;
        Fh[40 + pp]         = sqrtf(lx * lx + ly * ly + lz * lz);
    }
}

// ---------------- kOut: tiled split-K GEMM 512x384, K=2112 (validated) ----------------
__global__ void __launch_bounds__(256) kOut(const float* __restrict__ Wout)
{
    __shared__ float As[16 * 68];
    __shared__ float Bs[16 * 68];
    const int t  = threadIdx.x;
    const int c0 = blockIdx.x * 64;
    const int r0 = blockIdx.y * 64;
    const int k0 = blockIdx.z * 528;
    const int tx = t % 16, ty = t / 16;
    float acc[4][4];
    #pragma unroll
    for (int i = 0; i < 4; i++)
        #pragma unroll
        for (int j = 0; j < 4; j++) acc[i][j] = 0.f;

    for (int kt = 0; kt < 33; kt++) {
        const int kb = k0 + kt * 16;
        __syncthreads();
        #pragma unroll
        for (int ii = 0; ii < 4; ii++) {
            int i = t + 256 * ii;
            int row = i >> 4, k = i & 15;
            As[k * 68 + row] = g_F[(size_t)(r0 + row) * 2112 + kb + k];
        }
        #pragma unroll
        for (int ii = 0; ii < 4; ii++) {
            int i = t + 256 * ii;
            int k = i >> 6, c = i & 63;
            Bs[k * 68 + c] = Wout[(size_t)(kb + k) * 384 + c0 + c];
        }
        __syncthreads();
        #pragma unroll
        for (int k = 0; k < 16; k++) {
            float4 a = *(const float4*)&As[k * 68 + ty * 4];
            float4 b = *(const float4*)&Bs[k * 68 + tx * 4];
            float av[4] = {a.x, a.y, a.z, a.w};
            float bw[4] = {b.x, b.y, b.z, b.w};
            #pragma unroll
            for (int i = 0; i < 4; i++)
                #pragma unroll
                for (int j = 0; j < 4; j++) acc[i][j] += av[i] * bw[j];
        }
    }
    float* Pp = g_EP + (size_t)blockIdx.z * 512 * 384;
    #pragma unroll
    for (int i = 0; i < 4; i++) {
        float4 v = {acc[i][0], acc[i][1], acc[i][2], acc[i][3]};
        *(float4*)(Pp + (size_t)(r0 + ty * 4 + i) * 384 + c0 + tx * 4) = v;
    }
}

__global__ void __launch_bounds__(256) kOutRed(float* __restrict__ out,
                                               const float* __restrict__ bout)
{
    const int e = (blockIdx.x * 256 + threadIdx.x) * 4;
    float4 acc = *(const float4*)(bout + (e % 384));
    #pragma unroll
    for (int zz = 0; zz < 4; zz++) {
        float4 p = *(const float4*)(g_EP + (size_t)zz * 512 * 384 + e);
        acc.x += p.x; acc.y += p.y; acc.z += p.z; acc.w += p.w;
    }
    *(float4*)(out + e) = acc;
}

extern "C" void kernel_launch(void* const* d_in, const int* in_sizes, int n_in,
                              void* d_out, int out_size)
{
    const float* s     = (const float*)d_in[0];
    const float* z     = (const float*)d_in[1];
    const float* trans = (const float*)d_in[2];
    const float* rot   = (const float*)d_in[3];
    // d_in[4] = mask (all true; unused)
    const float* Wq  = (const float*)d_in[5];   const float* bq  = (const float*)d_in[6];
    const float* Wk  = (const float*)d_in[7];   const float* bk  = (const float*)d_in[8];
    const float* Wv  = (const float*)d_in[9];   const float* bv  = (const float*)d_in[10];
    const float* Wqp = (const float*)d_in[11];  const float* bqp = (const float*)d_in[12];
    const float* Wkp = (const float*)d_in[13];  const float* bkp = (const float*)d_in[14];
    const float* Wvp = (const float*)d_in[15];  const float* bvp = (const float*)d_in[16];
    const float* Wb  = (const float*)d_in[17];  const float* bb  = (const float*)d_in[18];
    const float* de  = (const float*)d_in[19];
    const float* sl  = (const float*)d_in[20];
    const float* hw  = (const float*)d_in[21];
    const float* Wout = (const float*)d_in[22];
    const float* bout = (const float*)d_in[23];
    float* out = (float*)d_out;

    cudaFuncSetAttribute(kApply4, cudaFuncAttributeMaxDynamicSharedMemorySize,
                         APPLY_SMEM_FLOATS * 4);

    kProj<<<dim3(18, 8), 256>>>(s, Wq, bq, Wk, bk, Wv, bv, Wqp, bqp, Wkp, bkp, Wvp, bvp);
    pTrans<<<512, 192>>>(trans, rot);
    pLogits3<<<256, 512>>>(z, trans, Wb, bb, de, sl, hw);
    kApply4<<<512, 672, APPLY_SMEM_FLOATS * 4>>>(z, trans, rot);
    kOut<<<dim3(6, 8, 4), 256>>>(Wout);
    kOutRed<<<192, 256>>>(out, bout);
}

// round 11
// speedup vs baseline: 1.8136x; 1.8136x over previous
#include <cuda_runtime.h>
#include <math.h>

__device__ float g_Q[512 * 192];
__device__ float g_K[512 * 192];
__device__ float g_V[512 * 192];
__device__ float g_QP[512 * 144];
__device__ float g_KP[512 * 144];
__device__ float g_VP[512 * 288];
__device__ float g_QG[512 * 144];
__device__ float g_KG[512 * 144];
__device__ float g_VG[512 * 288];
__device__ float g_F[512 * 2112];               // feats  [n][h*176 + f]
__device__ float g_EP[4 * 512 * 384];           // split-K partials

// ---------------- kProj: fused projection GEMM, 512 x 1152, K=384 (validated) ----------------
__device__ __forceinline__ void segSelW(int c,
    const float* Wq, const float* Wk, const float* Wv,
    const float* Wqp, const float* Wkp, const float* Wvp,
    const float*& W, int& lc, int& sn)
{
    if (c < 192)      { W = Wq;  lc = c;       sn = 192; }
    else if (c < 384) { W = Wk;  lc = c - 192; sn = 192; }
    else if (c < 576) { W = Wv;  lc = c - 384; sn = 192; }
    else if (c < 720) { W = Wqp; lc = c - 576; sn = 144; }
    else if (c < 864) { W = Wkp; lc = c - 720; sn = 144; }
    else              { W = Wvp; lc = c - 864; sn = 288; }
}

__device__ __forceinline__ void segSelO(int c,
    const float* bq, const float* bk, const float* bv,
    const float* bqp, const float* bkp, const float* bvp,
    float*& out, const float*& bia, int& lc, int& sn)
{
    if (c < 192)      { out = g_Q;  bia = bq;  lc = c;       sn = 192; }
    else if (c < 384) { out = g_K;  bia = bk;  lc = c - 192; sn = 192; }
    else if (c < 576) { out = g_V;  bia = bv;  lc = c - 384; sn = 192; }
    else if (c < 720) { out = g_QP; bia = bqp; lc = c - 576; sn = 144; }
    else if (c < 864) { out = g_KP; bia = bkp; lc = c - 720; sn = 144; }
    else              { out = g_VP; bia = bvp; lc = c - 864; sn = 288; }
}

__global__ void __launch_bounds__(256) kProj(
    const float* __restrict__ s,
    const float* __restrict__ Wq,  const float* __restrict__ bq,
    const float* __restrict__ Wk,  const float* __restrict__ bk,
    const float* __restrict__ Wv,  const float* __restrict__ bv,
    const float* __restrict__ Wqp, const float* __restrict__ bqp,
    const float* __restrict__ Wkp, const float* __restrict__ bkp,
    const float* __restrict__ Wvp, const float* __restrict__ bvp)
{
    __shared__ float As[32 * 68];
    __shared__ float Bs[32 * 68];
    const int t  = threadIdx.x;
    const int c0 = blockIdx.x * 64;
    const int r0 = blockIdx.y * 64;
    const int tx = t % 16, ty = t / 16;

    float acc[4][4];
    #pragma unroll
    for (int i = 0; i < 4; i++)
        #pragma unroll
        for (int j = 0; j < 4; j++) acc[i][j] = 0.f;

    for (int kt = 0; kt < 384; kt += 32) {
        __syncthreads();
        #pragma unroll
        for (int ii = 0; ii < 2; ii++) {
            int i4 = t + 256 * ii;
            int row = i4 >> 3, kq = i4 & 7;
            float4 a = *(const float4*)(s + (size_t)(r0 + row) * 384 + kt + kq * 4);
            As[(kq * 4 + 0) * 68 + row] = a.x;
            As[(kq * 4 + 1) * 68 + row] = a.y;
            As[(kq * 4 + 2) * 68 + row] = a.z;
            As[(kq * 4 + 3) * 68 + row] = a.w;
        }
        #pragma unroll
        for (int ii = 0; ii < 8; ii++) {
            int i = t + 256 * ii;
            int k = i >> 6, c = i & 63;
            const float* W; int lc, sn;
            segSelW(c0 + c, Wq, Wk, Wv, Wqp, Wkp, Wvp, W, lc, sn);
            Bs[k * 68 + c] = W[(size_t)(kt + k) * sn + lc];
        }
        __syncthreads();
        #pragma unroll
        for (int k = 0; k < 32; k++) {
            float4 a = *(const float4*)&As[k * 68 + ty * 4];
            float4 b = *(const float4*)&Bs[k * 68 + tx * 4];
            float av[4] = {a.x, a.y, a.z, a.w};
            float bw[4] = {b.x, b.y, b.z, b.w};
            #pragma unroll
            for (int i = 0; i < 4; i++)
                #pragma unroll
                for (int j = 0; j < 4; j++) acc[i][j] += av[i] * bw[j];
        }
    }
    float* out; const float* bia; int lc, sn;
    segSelO(c0 + tx * 4, bq, bk, bv, bqp, bkp, bvp, out, bia, lc, sn);
    float b0 = bia[lc], b1 = bia[lc + 1], b2 = bia[lc + 2], b3 = bia[lc + 3];
    #pragma unroll
    for (int i = 0; i < 4; i++) {
        int row = r0 + ty * 4 + i;
        float4 v = {acc[i][0] + b0, acc[i][1] + b1, acc[i][2] + b2, acc[i][3] + b3};
        *(float4*)(out + (size_t)row * sn + lc) = v;
    }
}

// ---------------- pTrans (validated) ----------------
__global__ void pTrans(const float* __restrict__ trans, const float* __restrict__ rot)
{
    const int n = blockIdx.x, t = threadIdx.x;   // 192 threads
    const float* R = rot + n * 9;
    const float T0 = trans[n * 3], T1 = trans[n * 3 + 1], T2 = trans[n * 3 + 2];
    const float* src; float* dst; int li;
    if (t < 48)      { src = g_QP + n * 144; dst = g_QG + n * 144; li = t; }
    else if (t < 96) { src = g_KP + n * 144; dst = g_KG + n * 144; li = t - 48; }
    else             { src = g_VP + n * 288; dst = g_VG + n * 288; li = t - 96; }
    float p0 = src[li * 3], p1 = src[li * 3 + 1], p2 = src[li * 3 + 2];
    dst[li * 3 + 0] = R[0] * p0 + R[1] * p1 + R[2] * p2 + T0;
    dst[li * 3 + 1] = R[3] * p0 + R[4] * p1 + R[5] * p2 + T1;
    dst[li * 3 + 2] = R[6] * p0 + R[7] * p1 + R[8] * p2 + T2;
}

// ---------------- kFuse: logits + online softmax + apply, z read once ----------------
__device__ __forceinline__ void cpAsync16(float* dst, const float* src)
{
    unsigned d = (unsigned)__cvta_generic_to_shared(dst);
    asm volatile("cp.async.cg.shared.global [%0], [%1], 16;" :: "r"(d), "l"(src));
}
#define CP_COMMIT() asm volatile("cp.async.commit_group;")
#define CP_WAIT1()  asm volatile("cp.async.wait_group 1;")
#define CP_WAIT0()  asm volatile("cp.async.wait_group 0;")

// smem: zt 2 x 32x132 | lt 32x13 | q 192 | qg 144 | Wb 1536 | de 768 | misc
__global__ void __launch_bounds__(512) kFuse(
    const float* __restrict__ z, const float* __restrict__ trans,
    const float* __restrict__ rot,
    const float* __restrict__ Wb, const float* __restrict__ bb,
    const float* __restrict__ de, const float* __restrict__ sl,
    const float* __restrict__ hw)
{
    __shared__ float zt[2 * 4224];   // 32 rows x 132 (padded)
    __shared__ float lt[416];        // 32 x 13 (padded): logits -> probs
    __shared__ float q[192], qg[144], sWb[1536], sde[768];
    __shared__ float ph[36], shw[12], sbb[12], sfac[12], rmx[12], rsm[12];

    const int n = blockIdx.x, t = threadIdx.x;

    // headers
    for (int i = t; i < 192; i += 512) q[i]  = g_Q[(size_t)n * 192 + i];
    for (int i = t; i < 144; i += 512) qg[i] = g_QG[(size_t)n * 144 + i];
    for (int i = t; i < 1536; i += 512) sWb[i] = Wb[i];
    for (int i = t; i < 768; i += 512) sde[i] = de[i];
    if (t < 12) {
        shw[t] = hw[t];
        sbb[t] = bb[t];
        rmx[t] = -1e30f;
        rsm[t] = 0.f;
        float a = sl[t], b2 = sl[12 + t], c = sl[24 + t];
        float mx = fmaxf(a, fmaxf(b2, c));
        float ea = expf(a - mx), eb = expf(b2 - mx), ec = expf(c - mx);
        float inv = 1.f / (ea + eb + ec);
        ph[t] = ea * inv; ph[12 + t] = eb * inv; ph[24 + t] = ec * inv;
    }
    const float tn0 = trans[n * 3], tn1 = trans[n * 3 + 1], tn2 = trans[n * 3 + 2];

    // prefetch tile 0
    {
        const int i4a = t, i4b = t + 512;
        int mm = i4a >> 5, c4 = i4a & 31;
        cpAsync16(&zt[mm * 132 + c4 * 4], z + ((size_t)n * 512 + mm) * 128 + c4 * 4);
        mm = i4b >> 5; c4 = i4b & 31;
        cpAsync16(&zt[mm * 132 + c4 * 4], z + ((size_t)n * 512 + mm) * 128 + c4 * 4);
        CP_COMMIT();
    }
    __syncthreads();

    // role setup (validated r8 mapping)
    const int wid = t >> 5, lane = t & 31;
    const int hb = (t >> 5) * 3;        // pair head base (t<128)
    const int cq = lane * 4;            // pair cols
    float pacc[3][4];
    #pragma unroll
    for (int i = 0; i < 3; i++)
        #pragma unroll
        for (int j = 0; j < 4; j++) pacc[i][j] = 0.f;
    const int js = t - 128;             // scalar lane
    const int hs = (js >= 0) ? js / 16 : 0;
    float sacc = 0.f;
    const int jp = t - 320;             // pts lane
    const int hp = (jp >= 0) ? jp / 8 : 0;
    float a0 = 0.f, a1 = 0.f, a2 = 0.f;
    // phase-L mapping
    const int Lmm = t / 12, Lh = t % 12;   // t<384

    for (int mt = 0; mt < 16; mt++) {
        const int m0 = mt * 32;
        const int cur = mt & 1;
        float* ztc = zt + cur * 4224;
        // prefetch next tile
        if (mt < 15) {
            float* ztn = zt + (1 - cur) * 4224;
            const int mb = m0 + 32;
            int mm = t >> 5, c4 = t & 31;
            cpAsync16(&ztn[mm * 132 + c4 * 4], z + ((size_t)n * 512 + mb + mm) * 128 + c4 * 4);
            mm = (t + 512) >> 5; c4 = t & 31;
            cpAsync16(&ztn[mm * 132 + c4 * 4], z + ((size_t)n * 512 + mb + mm) * 128 + c4 * 4);
            CP_COMMIT();
            CP_WAIT1();
        } else {
            CP_WAIT0();
        }
        __syncthreads();

        // ---- phase L: logits for 32 m x 12 h (validated formulas) ----
        if (t < 384) {
            const int m = m0 + Lmm;
            float pb = sbb[Lh];
            #pragma unroll 8
            for (int c4 = 0; c4 < 32; c4++) {
                float4 zz = *(const float4*)&ztc[Lmm * 132 + c4 * 4];
                const float* w = &sWb[c4 * 48];
                pb += zz.x * w[Lh] + zz.y * w[12 + Lh] + zz.z * w[24 + Lh] + zz.w * w[36 + Lh];
            }
            float dx = tn0 - trans[m * 3];
            float dy = tn1 - trans[m * 3 + 1];
            float dz = tn2 - trans[m * 3 + 2];
            float d  = sqrtf(dx * dx + dy * dy + dz * dz);
            int bin = min(max((int)ceilf(d * 2.0f) - 1, 0), 63);
            float lo = (d <= 5.0f) ? 1.f : 0.f;
            float me = (d > 5.0f && d <= 15.0f) ? 1.f : 0.f;
            const float* kr = g_K  + (size_t)m * 192 + Lh * 16;
            const float* kg = g_KG + (size_t)m * 144 + Lh * 12;
            float sc = 0.f;
            #pragma unroll
            for (int c = 0; c < 16; c++) sc += q[Lh * 16 + c] * kr[c];
            float pd = 0.f;
            #pragma unroll
            for (int i = 0; i < 12; i++) {
                float df = qg[Lh * 12 + i] - kg[i];
                pd += df * df;
            }
            lt[Lmm * 13 + Lh] = 0.25f * sc - 0.5f * pd * shw[Lh] + pb
                              + sde[bin * 12 + Lh] + lo * ph[Lh] + me * ph[12 + Lh] + ph[24 + Lh];
        }
        __syncthreads();

        // ---- phase S: online softmax update, warp per head ----
        if (wid < 12) {
            const int h = wid;
            float l = lt[lane * 13 + h];
            float tmax = l;
            #pragma unroll
            for (int o = 16; o; o >>= 1) tmax = fmaxf(tmax, __shfl_xor_sync(0xffffffffu, tmax, o));
            float om = rmx[h];
            float nm = fmaxf(om, tmax);
            float p = expf(l - nm);
            float tsum = p;
            #pragma unroll
            for (int o = 16; o; o >>= 1) tsum += __shfl_xor_sync(0xffffffffu, tsum, o);
            float f = expf(om - nm);
            lt[lane * 13 + h] = p;
            if (lane == 0) {
                rmx[h] = nm;
                rsm[h] = rsm[h] * f + tsum;
                sfac[h] = f;
            }
        }
        __syncthreads();

        // ---- phase A: rescale + accumulate (validated roles) ----
        if (t < 128) {
            #pragma unroll
            for (int hh = 0; hh < 3; hh++) {
                float f = sfac[hb + hh];
                #pragma unroll
                for (int j = 0; j < 4; j++) pacc[hh][j] *= f;
            }
            #pragma unroll 8
            for (int mm = 0; mm < 32; mm++) {
                float4 zz = *(const float4*)&ztc[mm * 132 + cq];
                #pragma unroll
                for (int hh = 0; hh < 3; hh++) {
                    float p = lt[mm * 13 + hb + hh];
                    pacc[hh][0] += p * zz.x; pacc[hh][1] += p * zz.y;
                    pacc[hh][2] += p * zz.z; pacc[hh][3] += p * zz.w;
                }
            }
        } else if (t < 320) {
            sacc *= sfac[hs];
            #pragma unroll 8
            for (int mm = 0; mm < 32; mm++)
                sacc += lt[mm * 13 + hs] * g_V[(size_t)(m0 + mm) * 192 + js];
        } else if (t < 416) {
            float f = sfac[hp];
            a0 *= f; a1 *= f; a2 *= f;
            #pragma unroll 8
            for (int mm = 0; mm < 32; mm++) {
                float pm = lt[mm * 13 + hp];
                const float* vg = g_VG + (size_t)(m0 + mm) * 288 + jp * 3;
                a0 += pm * vg[0]; a1 += pm * vg[1]; a2 += pm * vg[2];
            }
        }
        __syncthreads();
    }

    // epilogue: normalize + write (validated)
    if (t < 12) sfac[t] = 1.0f / rsm[t];
    __syncthreads();
    if (t < 128) {
        #pragma unroll
        for (int hh = 0; hh < 3; hh++) {
            float inv = sfac[hb + hh];
            float4 v = {pacc[hh][0] * inv, pacc[hh][1] * inv,
                        pacc[hh][2] * inv, pacc[hh][3] * inv};
            *(float4*)(g_F + (size_t)n * 2112 + (hb + hh) * 176 + 48 + cq) = v;
        }
    } else if (t < 320) {
        g_F[(size_t)n * 2112 + hs * 176 + (js % 16)] = sacc * sfac[hs];
    } else if (t < 416) {
        const int pp = jp % 8;
        float inv = sfac[hp];
        a0 = a0 * inv - tn0; a1 = a1 * inv - tn1; a2 = a2 * inv - tn2;
        const float* R = rot + n * 9;
        float lx = R[0] * a0 + R[3] * a1 + R[6] * a2;   // R^T
        float ly = R[1] * a0 + R[4] * a1 + R[7] * a2;
        float lz = R[2] * a0 + R[5] * a1 + R[8] * a2;
        float* Fh = g_F + (size_t)n * 2112 + hp * 176;
        Fh[16 + pp * 3]     = lx;
        Fh[16 + pp * 3 + 1] = ly;
        Fh[16 + pp * 3 + 2] = lz;
        Fh[40 + pp]         = sqrtf(lx * lx + ly * ly + lz * lz);
    }
}

// ---------------- kOut: tiled split-K GEMM 512x384, K=2112 (validated) ----------------
__global__ void __launch_bounds__(256) kOut(const float* __restrict__ Wout)
{
    __shared__ float As[16 * 68];
    __shared__ float Bs[16 * 68];
    const int t  = threadIdx.x;
    const int c0 = blockIdx.x * 64;
    const int r0 = blockIdx.y * 64;
    const int k0 = blockIdx.z * 528;
    const int tx = t % 16, ty = t / 16;
    float acc[4][4];
    #pragma unroll
    for (int i = 0; i < 4; i++)
        #pragma unroll
        for (int j = 0; j < 4; j++) acc[i][j] = 0.f;

    for (int kt = 0; kt < 33; kt++) {
        const int kb = k0 + kt * 16;
        __syncthreads();
        #pragma unroll
        for (int ii = 0; ii < 4; ii++) {
            int i = t + 256 * ii;
            int row = i >> 4, k = i & 15;
            As[k * 68 + row] = g_F[(size_t)(r0 + row) * 2112 + kb + k];
        }
        #pragma unroll
        for (int ii = 0; ii < 4; ii++) {
            int i = t + 256 * ii;
            int k = i >> 6, c = i & 63;
            Bs[k * 68 + c] = Wout[(size_t)(kb + k) * 384 + c0 + c];
        }
        __syncthreads();
        #pragma unroll
        for (int k = 0; k < 16; k++) {
            float4 a = *(const float4*)&As[k * 68 + ty * 4];
            float4 b = *(const float4*)&Bs[k * 68 + tx * 4];
            float av[4] = {a.x, a.y, a.z, a.w};
            float bw[4] = {b.x, b.y, b.z, b.w};
            #pragma unroll
            for (int i = 0; i < 4; i++)
                #pragma unroll
                for (int j = 0; j < 4; j++) acc[i][j] += av[i] * bw[j];
        }
    }
    float* Pp = g_EP + (size_t)blockIdx.z * 512 * 384;
    #pragma unroll
    for (int i = 0; i < 4; i++) {
        float4 v = {acc[i][0], acc[i][1], acc[i][2], acc[i][3]};
        *(float4*)(Pp + (size_t)(r0 + ty * 4 + i) * 384 + c0 + tx * 4) = v;
    }
}

__global__ void __launch_bounds__(256) kOutRed(float* __restrict__ out,
                                               const float* __restrict__ bout)
{
    const int e = (blockIdx.x * 256 + threadIdx.x) * 4;
    float4 acc = *(const float4*)(bout + (e % 384));
    #pragma unroll
    for (int zz = 0; zz < 4; zz++) {
        float4 p = *(const float4*)(g_EP + (size_t)zz * 512 * 384 + e);
        acc.x += p.x; acc.y += p.y; acc.z += p.z; acc.w += p.w;
    }
    *(float4*)(out + e) = acc;
}

extern "C" void kernel_launch(void* const* d_in, const int* in_sizes, int n_in,
                              void* d_out, int out_size)
{
    const float* s     = (const float*)d_in[0];
    const float* z     = (const float*)d_in[1];
    const float* trans = (const float*)d_in[2];
    const float* rot   = (const float*)d_in[3];
    // d_in[4] = mask (all true; unused)
    const float* Wq  = (const float*)d_in[5];   const float* bq  = (const float*)d_in[6];
    const float* Wk  = (const float*)d_in[7];   const float* bk  = (const float*)d_in[8];
    const float* Wv  = (const float*)d_in[9];   const float* bv  = (const float*)d_in[10];
    const float* Wqp = (const float*)d_in[11];  const float* bqp = (const float*)d_in[12];
    const float* Wkp = (const float*)d_in[13];  const float* bkp = (const float*)d_in[14];
    const float* Wvp = (const float*)d_in[15];  const float* bvp = (const float*)d_in[16];
    const float* Wb  = (const float*)d_in[17];  const float* bb  = (const float*)d_in[18];
    const float* de  = (const float*)d_in[19];
    const float* sl  = (const float*)d_in[20];
    const float* hw  = (const float*)d_in[21];
    const float* Wout = (const float*)d_in[22];
    const float* bout = (const float*)d_in[23];
    float* out = (float*)d_out;

    kProj<<<dim3(18, 8), 256>>>(s, Wq, bq, Wk, bk, Wv, bv, Wqp, bqp, Wkp, bkp, Wvp, bvp);
    pTrans<<<512, 192>>>(trans, rot);
    kFuse<<<512, 512>>>(z, trans, rot, Wb, bb, de, sl, hw);
    kOut<<<dim3(6, 8, 4), 256>>>(Wout);
    kOutRed<<<192, 256>>>(out, bout);
}